// round 11
// baseline (speedup 1.0000x reference)
#include <cuda_runtime.h>
#include <cuda_fp16.h>
#include <cstdint>

#define NN 100000
#define NE 1600000
#define HH 128
#define ZC 20
#define NB 782            // ceil(NN/128)
#define PITCH 136         // smem row pitch in halves
#define TILE_GB 32768     // 128x128 fp16 tile bytes
#define SCAN_BLK 1024
#define NSCAN 98          // ceil(NN/1024)

// ---- scratch (device globals: allocation-free) ----
__device__ __align__(16) float g_dinv[NN];
__device__ __align__(16) uint32_t g_xh[NN * 64];           // xs = x*dinv, half2 pairs
__device__ __align__(16) __half g_Zh[NN * ZC];             // Z' = readout * dinv (fp16)
__device__ __align__(16) float g_c[ZC];
__device__ __align__(16) unsigned char g_Wh[7 * TILE_GB];  // W^T fp16 [f][h]
__device__ __align__(16) float g_BM[7 * HH * 4];           // {bias, M0, M1, M2}
// CSR (in-edges grouped by dst); row becomes END cursor after scatter
__device__ __align__(16) int g_cnt[NN];
__device__ __align__(16) int g_row[NN];
__device__ __align__(16) int g_srcl[NE];
__device__ int g_bsum[NSCAN];

__device__ __forceinline__ uint32_t smem_u32(const void* p) {
    uint32_t a;
    asm("{ .reg .u64 t; cvta.to.shared.u64 t, %1; cvt.u32.u64 %0, t; }" : "=r"(a) : "l"(p));
    return a;
}

// ================= CSR build =================
__global__ void k_init() {
    int i = blockIdx.x * blockDim.x + threadIdx.x;
    if (i < NN) g_cnt[i] = 0;
}
__global__ void k_count(const int4* __restrict__ dst4) {
    int t = blockIdx.x * blockDim.x + threadIdx.x;
    if (t >= NE / 4) return;
    int4 d = dst4[t];
    atomicAdd(&g_cnt[d.x], 1);
    atomicAdd(&g_cnt[d.y], 1);
    atomicAdd(&g_cnt[d.z], 1);
    atomicAdd(&g_cnt[d.w], 1);
}
__global__ void k_scan1() {   // also computes dinv
    __shared__ int sd[SCAN_BLK];
    int tid = threadIdx.x, i = blockIdx.x * SCAN_BLK + tid;
    int v = (i < NN) ? g_cnt[i] : 0;
    if (i < NN) g_dinv[i] = rsqrtf((float)v + 1.0f);
    sd[tid] = v;
    __syncthreads();
    for (int off = 1; off < SCAN_BLK; off <<= 1) {
        int t = (tid >= off) ? sd[tid - off] : 0;
        __syncthreads();
        sd[tid] += t;
        __syncthreads();
    }
    if (i < NN) g_row[i] = sd[tid] - v;   // exclusive start (block-local)
    if (tid == SCAN_BLK - 1) g_bsum[blockIdx.x] = sd[tid];
}
// cross-block prefix folded in: warp 0 sums g_bsum[0..blk-1], blk = blockIdx>>2
__global__ void k_scan3() {
    __shared__ int sbase;
    int tid = threadIdx.x;
    int blk = blockIdx.x >> 2;       // 1024 / 256
    if (tid < 32) {
        int s = 0;
        for (int j = tid; j < blk; j += 32) s += g_bsum[j];
        #pragma unroll
        for (int off = 16; off; off >>= 1) s += __shfl_xor_sync(0xffffffffu, s, off);
        if (tid == 0) sbase = s;
    }
    __syncthreads();
    int i = blockIdx.x * blockDim.x + tid;
    if (i < NN) g_row[i] += sbase;
}
__global__ void k_scatter(const int* __restrict__ ei) {
    int e = blockIdx.x * blockDim.x + threadIdx.x;
    if (e >= NE) return;
    int s = ei[e];
    int d = ei[NE + e];
    int pos = atomicAdd(&g_row[d], 1);
    g_srcl[pos] = s;
}

// ================= xs = x * dinv -> fp16 =================
__global__ void k_xh(const float4* __restrict__ x4) {
    int idx = blockIdx.x * blockDim.x + threadIdx.x;
    if (idx >= NN * 32) return;
    int n = idx >> 5;
    float di = g_dinv[n];
    float4 v = x4[idx];
    __half2 p0 = __floats2half2_rn(v.x * di, v.y * di);
    __half2 p1 = __floats2half2_rn(v.z * di, v.w * di);
    uint2 w;
    w.x = *(uint32_t*)&p0;
    w.y = *(uint32_t*)&p1;
    *(uint2*)&g_xh[(size_t)n * 64 + (idx & 31) * 2] = w;
}

// ================= weight prep =================
__global__ void k_mc(const float* __restrict__ gw_, const float* __restrict__ gb,
                     const float* __restrict__ r3w, const float* __restrict__ r3b,
                     const float* __restrict__ r2w, const float* __restrict__ r2b) {
    int t = blockIdx.x * blockDim.x + threadIdx.x;
    if (t >= 19 * HH) return;
    int col = t / HH, h = t % HH;
    int k; const float* R; float rb;
    if (col < 15) { k = col / 3; int c = col % 3; R = r3w + (k * 3 + c) * HH; rb = r3b[k * 3 + c]; }
    else { int cc = col - 15; k = 5 + cc / 2; int c = cc % 2; R = r2w + ((k - 5) * 2 + c) * HH; rb = r2b[(k - 5) * 2 + c]; }
    const float* Wrow = gw_ + k * HH * HH + h * HH;
    float acc = 0.f;
    #pragma unroll 8
    for (int j = 0; j < HH; j++) acc = fmaf(Wrow[j], R[j], acc);
    int colbase = (k < 5) ? 3 * k : 15 + 2 * (k - 5);
    g_BM[(k * HH + h) * 4 + 1 + (col - colbase)] = acc;
    if (t < 7 * HH) {
        int k2 = t >> 7, f = t & 127;
        g_BM[t * 4] = gb[k2 * HH + f];
        if (k2 >= 5) g_BM[t * 4 + 3] = 0.f;
    }
    if (h == 0) {
        const float* b = gb + k * HH;
        float cb = 0.f;
        #pragma unroll 8
        for (int j = 0; j < HH; j++) cb = fmaf(b[j], R[j], cb);
        g_c[col] = cb + rb;
    }
    if (t == 0) g_c[19] = 0.f;
}

__global__ void k_prep_w(const float* __restrict__ gw_) {
    int t = blockIdx.x * blockDim.x + threadIdx.x;
    if (t >= 7 * 128 * 64) return;
    int k = t / 8192, r = t % 8192, f = r / 64, h = (r % 64) * 2;
    float w0 = gw_[k * 16384 + h * 128 + f];
    float w1 = gw_[k * 16384 + (h + 1) * 128 + f];
    __half h0 = __float2half_rn(w0), h1 = __float2half_rn(w1);
    int off = f * 256 + h * 2;
    *(uint32_t*)(g_Wh + k * TILE_GB + off) =
        ((uint32_t)__half_as_ushort(h1) << 16) | __half_as_ushort(h0);
}

// ================= fused gather + HMMA branch kernel (2 CTAs/SM) =========
// Prologue: each warp CSR-gathers its 16 nodes' y rows straight into A smem.
__global__ void __launch_bounds__(256, 2) k_branch() {
    extern __shared__ __align__(16) unsigned char sm[];
    const int A_OFF = 0;
    const int B_OFF = A_OFF + 128 * PITCH * 2;
    uint32_t sb = smem_u32(sm);
    int tid = threadIdx.x;
    int w = tid >> 5, lane = tid & 31;
    int n0 = blockIdx.x * 128;

    // ---- fused y = A_hat x gather (warp per node, 16 nodes per warp) ----
    {
        const uint2* xh = (const uint2*)g_xh;
        for (int i = 0; i < 16; i++) {
            int n = n0 + w * 16 + i;
            uint2 wv = make_uint2(0u, 0u);
            if (n < NN) {
                int end = g_row[n], e = end - g_cnt[n];
                uint2 sv = xh[(size_t)n * 32 + lane];
                float2 f0 = __half22float2(*(__half2*)&sv.x);
                float2 f1 = __half22float2(*(__half2*)&sv.y);
                float a0 = f0.x, a1 = f0.y, a2 = f1.x, a3 = f1.y;
                for (; e + 3 < end; e += 4) {
                    int q0 = g_srcl[e], q1 = g_srcl[e + 1];
                    int q2 = g_srcl[e + 2], q3 = g_srcl[e + 3];
                    uint2 v0 = xh[(size_t)q0 * 32 + lane];
                    uint2 v1 = xh[(size_t)q1 * 32 + lane];
                    uint2 v2 = xh[(size_t)q2 * 32 + lane];
                    uint2 v3 = xh[(size_t)q3 * 32 + lane];
                    float2 u0 = __half22float2(*(__half2*)&v0.x), u1 = __half22float2(*(__half2*)&v0.y);
                    float2 u2 = __half22float2(*(__half2*)&v1.x), u3 = __half22float2(*(__half2*)&v1.y);
                    float2 u4 = __half22float2(*(__half2*)&v2.x), u5 = __half22float2(*(__half2*)&v2.y);
                    float2 u6 = __half22float2(*(__half2*)&v3.x), u7 = __half22float2(*(__half2*)&v3.y);
                    a0 += (u0.x + u2.x) + (u4.x + u6.x);
                    a1 += (u0.y + u2.y) + (u4.y + u6.y);
                    a2 += (u1.x + u3.x) + (u5.x + u7.x);
                    a3 += (u1.y + u3.y) + (u5.y + u7.y);
                }
                for (; e < end; e++) {
                    int q0 = g_srcl[e];
                    uint2 v0 = xh[(size_t)q0 * 32 + lane];
                    float2 u0 = __half22float2(*(__half2*)&v0.x), u1 = __half22float2(*(__half2*)&v0.y);
                    a0 += u0.x; a1 += u0.y; a2 += u1.x; a3 += u1.y;
                }
                float di = g_dinv[n];
                __half2 p0 = __floats2half2_rn(a0 * di, a1 * di);
                __half2 p1 = __floats2half2_rn(a2 * di, a3 * di);
                wv.x = *(uint32_t*)&p0;
                wv.y = *(uint32_t*)&p1;
            }
            *(uint2*)(sm + A_OFF + (w * 16 + i) * (PITCH * 2) + lane * 8) = wv;
        }
    }

    int a_row = lane & 15, a_cb = (lane >> 4) * 8;
    int b_row = ((lane >> 4) * 8) + (lane & 7);
    int b_kb = ((lane >> 3) & 1) * 8;
    const float4* bmt = (const float4*)g_BM;

    for (int k = 0; k < 7; k++) {
        __syncthreads();
        {
            const uint4* sh = (const uint4*)(g_Wh + k * TILE_GB);
            for (int i = tid; i < 2048; i += 256) {
                int f = i >> 4, seg = i & 15;
                *(uint4*)(sm + B_OFF + f * (PITCH * 2) + seg * 16) = sh[i];
            }
        }
        __syncthreads();

        float acc[16][4];
        #pragma unroll
        for (int t = 0; t < 16; t++)
            #pragma unroll
            for (int j = 0; j < 4; j++) acc[t][j] = 0.f;

        #pragma unroll
        for (int ks = 0; ks < 8; ks++) {
            uint32_t a0, a1, a2, a3;
            uint32_t aaddr = sb + A_OFF + (w * 16 + a_row) * (PITCH * 2) + (ks * 16 + a_cb) * 2;
            asm volatile("ldmatrix.sync.aligned.m8n8.x4.shared.b16 {%0,%1,%2,%3}, [%4];"
                         : "=r"(a0), "=r"(a1), "=r"(a2), "=r"(a3) : "r"(aaddr));
            #pragma unroll
            for (int p = 0; p < 8; p++) {
                uint32_t b0, b1, b2, b3;
                uint32_t baddr = sb + B_OFF + (p * 16 + b_row) * (PITCH * 2) + (ks * 16 + b_kb) * 2;
                asm volatile("ldmatrix.sync.aligned.m8n8.x4.shared.b16 {%0,%1,%2,%3}, [%4];"
                             : "=r"(b0), "=r"(b1), "=r"(b2), "=r"(b3) : "r"(baddr));
                asm volatile(
                    "mma.sync.aligned.m16n8k16.row.col.f32.f16.f16.f32 "
                    "{%0,%1,%2,%3}, {%4,%5,%6,%7}, {%8,%9}, {%0,%1,%2,%3};"
                    : "+f"(acc[2*p][0]), "+f"(acc[2*p][1]), "+f"(acc[2*p][2]), "+f"(acc[2*p][3])
                    : "r"(a0), "r"(a1), "r"(a2), "r"(a3), "r"(b0), "r"(b1));
                asm volatile(
                    "mma.sync.aligned.m16n8k16.row.col.f32.f16.f16.f32 "
                    "{%0,%1,%2,%3}, {%4,%5,%6,%7}, {%8,%9}, {%0,%1,%2,%3};"
                    : "+f"(acc[2*p+1][0]), "+f"(acc[2*p+1][1]), "+f"(acc[2*p+1][2]), "+f"(acc[2*p+1][3])
                    : "r"(a0), "r"(a1), "r"(a2), "r"(a3), "r"(b2), "r"(b3));
            }
        }

        int gr = lane >> 2, cq = (lane & 3) * 2;
        float zA0 = 0.f, zA1 = 0.f, zA2 = 0.f, zB0 = 0.f, zB1 = 0.f, zB2 = 0.f;
        #pragma unroll
        for (int nt = 0; nt < 16; nt++) {
            float4 m0 = __ldg(&bmt[k * HH + nt * 8 + cq]);
            float4 m1 = __ldg(&bmt[k * HH + nt * 8 + cq + 1]);
            float hA0 = fmaxf(acc[nt][0] + m0.x, 0.f);
            float hA1 = fmaxf(acc[nt][1] + m1.x, 0.f);
            float hB0 = fmaxf(acc[nt][2] + m0.x, 0.f);
            float hB1 = fmaxf(acc[nt][3] + m1.x, 0.f);
            zA0 = fmaf(hA0, m0.y, fmaf(hA1, m1.y, zA0));
            zA1 = fmaf(hA0, m0.z, fmaf(hA1, m1.z, zA1));
            zA2 = fmaf(hA0, m0.w, fmaf(hA1, m1.w, zA2));
            zB0 = fmaf(hB0, m0.y, fmaf(hB1, m1.y, zB0));
            zB1 = fmaf(hB0, m0.z, fmaf(hB1, m1.z, zB1));
            zB2 = fmaf(hB0, m0.w, fmaf(hB1, m1.w, zB2));
        }
        #pragma unroll
        for (int off = 1; off < 4; off <<= 1) {
            zA0 += __shfl_xor_sync(0xffffffffu, zA0, off);
            zA1 += __shfl_xor_sync(0xffffffffu, zA1, off);
            zA2 += __shfl_xor_sync(0xffffffffu, zA2, off);
            zB0 += __shfl_xor_sync(0xffffffffu, zB0, off);
            zB1 += __shfl_xor_sync(0xffffffffu, zB1, off);
            zB2 += __shfl_xor_sync(0xffffffffu, zB2, off);
        }
        if ((lane & 3) == 0) {
            int colbase = (k < 5) ? 3 * k : 15 + 2 * (k - 5);
            int ncol = (k < 5) ? 3 : 2;
            int rowA = n0 + w * 16 + gr, rowB = rowA + 8;
            if (rowA < NN) {
                float di = g_dinv[rowA];
                __half* zp = &g_Zh[(size_t)rowA * ZC + colbase];
                zp[0] = __float2half_rn(zA0 * di);
                zp[1] = __float2half_rn(zA1 * di);
                if (ncol == 3) zp[2] = __float2half_rn(zA2 * di);
            }
            if (rowB < NN) {
                float di = g_dinv[rowB];
                __half* zp = &g_Zh[(size_t)rowB * ZC + colbase];
                zp[0] = __float2half_rn(zB0 * di);
                zp[1] = __float2half_rn(zB1 * di);
                if (ncol == 3) zp[2] = __float2half_rn(zB2 * di);
            }
        }
    }
}

// ================= fused CSR-aggregate + softmax (warp per node) =================
__global__ void k_softmax_fused(float* __restrict__ out) {
    int n = (blockIdx.x * blockDim.x + threadIdx.x) >> 5;
    int lane = threadIdx.x & 31;
    if (n >= NN) return;
    bool active = lane < 19;
    int zlane = active ? lane : 0;
    float acc = active ? __half2float(g_Zh[(size_t)n * ZC + lane]) : 0.f;
    int end = g_row[n], e = end - g_cnt[n];
    for (; e + 3 < end; e += 4) {
        int s0 = g_srcl[e], s1 = g_srcl[e + 1], s2 = g_srcl[e + 2], s3 = g_srcl[e + 3];
        float v0 = __half2float(g_Zh[(size_t)s0 * ZC + zlane]);
        float v1 = __half2float(g_Zh[(size_t)s1 * ZC + zlane]);
        float v2 = __half2float(g_Zh[(size_t)s2 * ZC + zlane]);
        float v3 = __half2float(g_Zh[(size_t)s3 * ZC + zlane]);
        acc += (v0 + v1) + (v2 + v3);
    }
    for (; e < end; e++) {
        int s0 = g_srcl[e];
        acc += __half2float(g_Zh[(size_t)s0 * ZC + zlane]);
    }
    float di = g_dinv[n];
    float p = active ? fmaf(acc, di, g_c[lane]) : -1e30f;

    int base, ncol, j;
    if (lane < 15) { base = lane - (lane % 3); ncol = 3; j = lane - base; }
    else { base = 15 + ((lane - 15) & ~1); ncol = 2; j = lane - base; }
    float v0 = __shfl_sync(0xffffffffu, p, base);
    float v1 = __shfl_sync(0xffffffffu, p, base + 1);
    float v2 = (ncol == 3) ? __shfl_sync(0xffffffffu, p, base + 2) : -1e30f;
    float m = fmaxf(v0, fmaxf(v1, v2));
    float sum = __expf(v0 - m) + __expf(v1 - m) + ((ncol == 3) ? __expf(v2 - m) : 0.f);
    float mine = __expf(p - m) / sum;
    if (active)
        out[(long)base * NN + (long)n * ncol + j] = mine;
}

extern "C" void kernel_launch(void* const* d_in, const int* in_sizes, int n_in,
                              void* d_out, int out_size) {
    const float* x   = (const float*)d_in[0];
    const int*   ei  = (const int*)d_in[1];
    const float* gw_ = (const float*)d_in[2];
    const float* gb  = (const float*)d_in[3];
    const float* r3w = (const float*)d_in[4];
    const float* r3b = (const float*)d_in[5];
    const float* r2w = (const float*)d_in[6];
    const float* r2b = (const float*)d_in[7];
    float* out = (float*)d_out;

    const int SMEM = 2 * 128 * PITCH * 2;   // 69632
    static int once = 0;
    if (!once) {
        cudaFuncSetAttribute(k_branch, cudaFuncAttributeMaxDynamicSharedMemorySize, SMEM);
        once = 1;
    }

    // CSR build
    k_init<<<(NN + 255) / 256, 256>>>();
    k_count<<<(NE / 4 + 255) / 256, 256>>>((const int4*)(ei + NE));
    k_scan1<<<NSCAN, SCAN_BLK>>>();
    k_scan3<<<(NN + 255) / 256, 256>>>();
    k_scatter<<<(NE + 255) / 256, 256>>>(ei);
    // fp16 conversions + weight prep
    k_xh<<<(NN * 32 + 255) / 256, 256>>>((const float4*)x);
    k_mc<<<(19 * HH + 127) / 128, 128>>>(gw_, gb, r3w, r3b, r2w, r2b);
    k_prep_w<<<(7 * 128 * 64 + 127) / 128, 128>>>(gw_);
    // main pipeline (gather fused into branch prologue)
    k_branch<<<NB, 256, SMEM>>>();
    k_softmax_fused<<<(NN * 32 + 255) / 256, 256>>>(out);
}

// round 12
// speedup vs baseline: 1.2163x; 1.2163x over previous
#include <cuda_runtime.h>
#include <cuda_fp16.h>
#include <cstdint>

#define NN 100000
#define NE 1600000
#define HH 128
#define ZC 20
#define NB 782            // ceil(NN/128)
#define PITCH 136         // smem row pitch in halves
#define TILE_GB 32768     // 128x128 fp16 tile bytes
#define SCAN_BLK 1024
#define NSCAN 98          // ceil(NN/1024)

// ---- scratch (device globals: allocation-free) ----
__device__ __align__(16) float g_dinv[NN];
__device__ __align__(16) uint32_t g_xh[NN * 64];           // xs = x*dinv, half2 pairs
__device__ __align__(16) uint32_t g_yh[NN * 64];           // y, half2 pairs
__device__ __align__(16) __half g_Zh[NN * ZC];             // Z' = readout * dinv (fp16)
__device__ __align__(16) float g_c[ZC];
__device__ __align__(16) unsigned char g_Wh[7 * TILE_GB];  // W^T fp16 [f][h]
__device__ __align__(16) float g_BM[7 * HH * 4];           // {bias, M0, M1, M2}
// CSR (in-edges grouped by dst); row becomes END cursor after scatter
__device__ __align__(16) int g_cnt[NN];
__device__ __align__(16) int g_row[NN];
__device__ __align__(16) int g_srcl[NE];
__device__ int g_bsum[NSCAN];

__device__ __forceinline__ uint32_t smem_u32(const void* p) {
    uint32_t a;
    asm("{ .reg .u64 t; cvta.to.shared.u64 t, %1; cvt.u32.u64 %0, t; }" : "=r"(a) : "l"(p));
    return a;
}
__device__ __forceinline__ void cp_async16(uint32_t smem_dst, const void* gmem_src) {
    asm volatile("cp.async.cg.shared.global [%0], [%1], 16;"
                 :: "r"(smem_dst), "l"(gmem_src) : "memory");
}

// ================= CSR build =================
__global__ void k_init() {
    int i = blockIdx.x * blockDim.x + threadIdx.x;
    if (i < NN) g_cnt[i] = 0;
}
__global__ void k_count(const int4* __restrict__ dst4) {
    int t = blockIdx.x * blockDim.x + threadIdx.x;
    if (t >= NE / 4) return;
    int4 d = dst4[t];
    atomicAdd(&g_cnt[d.x], 1);
    atomicAdd(&g_cnt[d.y], 1);
    atomicAdd(&g_cnt[d.z], 1);
    atomicAdd(&g_cnt[d.w], 1);
}
__global__ void k_scan1() {   // also computes dinv
    __shared__ int sd[SCAN_BLK];
    int tid = threadIdx.x, i = blockIdx.x * SCAN_BLK + tid;
    int v = (i < NN) ? g_cnt[i] : 0;
    if (i < NN) g_dinv[i] = rsqrtf((float)v + 1.0f);
    sd[tid] = v;
    __syncthreads();
    for (int off = 1; off < SCAN_BLK; off <<= 1) {
        int t = (tid >= off) ? sd[tid - off] : 0;
        __syncthreads();
        sd[tid] += t;
        __syncthreads();
    }
    if (i < NN) g_row[i] = sd[tid] - v;   // exclusive start (block-local)
    if (tid == SCAN_BLK - 1) g_bsum[blockIdx.x] = sd[tid];
}
// cross-block prefix folded in: warp 0 sums g_bsum[0..blk-1], blk = blockIdx>>2
__global__ void k_scan3() {
    __shared__ int sbase;
    int tid = threadIdx.x;
    int blk = blockIdx.x >> 2;       // 1024 / 256
    if (tid < 32) {
        int s = 0;
        for (int j = tid; j < blk; j += 32) s += g_bsum[j];
        #pragma unroll
        for (int off = 16; off; off >>= 1) s += __shfl_xor_sync(0xffffffffu, s, off);
        if (tid == 0) sbase = s;
    }
    __syncthreads();
    int i = blockIdx.x * blockDim.x + tid;
    if (i < NN) g_row[i] += sbase;
}
__global__ void k_scatter(const int* __restrict__ ei) {
    int e = blockIdx.x * blockDim.x + threadIdx.x;
    if (e >= NE) return;
    int s = ei[e];
    int d = ei[NE + e];
    int pos = atomicAdd(&g_row[d], 1);
    g_srcl[pos] = s;
}

// ================= xs = x * dinv -> fp16 =================
__global__ void k_xh(const float4* __restrict__ x4) {
    int idx = blockIdx.x * blockDim.x + threadIdx.x;
    if (idx >= NN * 32) return;
    int n = idx >> 5;
    float di = g_dinv[n];
    float4 v = x4[idx];
    __half2 p0 = __floats2half2_rn(v.x * di, v.y * di);
    __half2 p1 = __floats2half2_rn(v.z * di, v.w * di);
    uint2 w;
    w.x = *(uint32_t*)&p0;
    w.y = *(uint32_t*)&p1;
    *(uint2*)&g_xh[(size_t)n * 64 + (idx & 31) * 2] = w;
}

// ================= y = A_hat x (CSR fp16 gather, warp per node) =============
__global__ void k_agg_y_csr() {
    int n = (blockIdx.x * blockDim.x + threadIdx.x) >> 5;
    int lane = threadIdx.x & 31;
    if (n >= NN) return;
    int end = g_row[n], e = end - g_cnt[n];
    const uint2* xh = (const uint2*)g_xh;
    uint2 sv = xh[(size_t)n * 32 + lane];
    float2 f0 = __half22float2(*(__half2*)&sv.x);
    float2 f1 = __half22float2(*(__half2*)&sv.y);
    float a0 = f0.x, a1 = f0.y, a2 = f1.x, a3 = f1.y;
    for (; e + 3 < end; e += 4) {
        int q0 = g_srcl[e], q1 = g_srcl[e + 1];
        int q2 = g_srcl[e + 2], q3 = g_srcl[e + 3];
        uint2 v0 = xh[(size_t)q0 * 32 + lane];
        uint2 v1 = xh[(size_t)q1 * 32 + lane];
        uint2 v2 = xh[(size_t)q2 * 32 + lane];
        uint2 v3 = xh[(size_t)q3 * 32 + lane];
        float2 u0 = __half22float2(*(__half2*)&v0.x), u1 = __half22float2(*(__half2*)&v0.y);
        float2 u2 = __half22float2(*(__half2*)&v1.x), u3 = __half22float2(*(__half2*)&v1.y);
        float2 u4 = __half22float2(*(__half2*)&v2.x), u5 = __half22float2(*(__half2*)&v2.y);
        float2 u6 = __half22float2(*(__half2*)&v3.x), u7 = __half22float2(*(__half2*)&v3.y);
        a0 += (u0.x + u2.x) + (u4.x + u6.x);
        a1 += (u0.y + u2.y) + (u4.y + u6.y);
        a2 += (u1.x + u3.x) + (u5.x + u7.x);
        a3 += (u1.y + u3.y) + (u5.y + u7.y);
    }
    for (; e < end; e++) {
        int q0 = g_srcl[e];
        uint2 v0 = xh[(size_t)q0 * 32 + lane];
        float2 u0 = __half22float2(*(__half2*)&v0.x), u1 = __half22float2(*(__half2*)&v0.y);
        a0 += u0.x; a1 += u0.y; a2 += u1.x; a3 += u1.y;
    }
    float di = g_dinv[n];
    __half2 p0 = __floats2half2_rn(a0 * di, a1 * di);
    __half2 p1 = __floats2half2_rn(a2 * di, a3 * di);
    uint2 w;
    w.x = *(uint32_t*)&p0;
    w.y = *(uint32_t*)&p1;
    *(uint2*)&g_yh[(size_t)n * 64 + lane * 2] = w;
}

// ================= weight prep =================
__global__ void k_mc(const float* __restrict__ gw_, const float* __restrict__ gb,
                     const float* __restrict__ r3w, const float* __restrict__ r3b,
                     const float* __restrict__ r2w, const float* __restrict__ r2b) {
    int t = blockIdx.x * blockDim.x + threadIdx.x;
    if (t >= 19 * HH) return;
    int col = t / HH, h = t % HH;
    int k; const float* R; float rb;
    if (col < 15) { k = col / 3; int c = col % 3; R = r3w + (k * 3 + c) * HH; rb = r3b[k * 3 + c]; }
    else { int cc = col - 15; k = 5 + cc / 2; int c = cc % 2; R = r2w + ((k - 5) * 2 + c) * HH; rb = r2b[(k - 5) * 2 + c]; }
    const float* Wrow = gw_ + k * HH * HH + h * HH;
    float acc = 0.f;
    #pragma unroll 8
    for (int j = 0; j < HH; j++) acc = fmaf(Wrow[j], R[j], acc);
    int colbase = (k < 5) ? 3 * k : 15 + 2 * (k - 5);
    g_BM[(k * HH + h) * 4 + 1 + (col - colbase)] = acc;
    if (t < 7 * HH) {
        int k2 = t >> 7, f = t & 127;
        g_BM[t * 4] = gb[k2 * HH + f];
        if (k2 >= 5) g_BM[t * 4 + 3] = 0.f;
    }
    if (h == 0) {
        const float* b = gb + k * HH;
        float cb = 0.f;
        #pragma unroll 8
        for (int j = 0; j < HH; j++) cb = fmaf(b[j], R[j], cb);
        g_c[col] = cb + rb;
    }
    if (t == 0) g_c[19] = 0.f;
}

__global__ void k_prep_w(const float* __restrict__ gw_) {
    int t = blockIdx.x * blockDim.x + threadIdx.x;
    if (t >= 7 * 128 * 64) return;
    int k = t / 8192, r = t % 8192, f = r / 64, h = (r % 64) * 2;
    float w0 = gw_[k * 16384 + h * 128 + f];
    float w1 = gw_[k * 16384 + (h + 1) * 128 + f];
    __half h0 = __float2half_rn(w0), h1 = __float2half_rn(w1);
    int off = f * 256 + h * 2;
    *(uint32_t*)(g_Wh + k * TILE_GB + off) =
        ((uint32_t)__half_as_ushort(h1) << 16) | __half_as_ushort(h0);
}

// ====== HMMA branch kernel (fp16 single pass, cp.async double-buffered W) ======
__global__ void __launch_bounds__(256, 2) k_branch() {
    extern __shared__ __align__(16) unsigned char sm[];
    const int A_OFF = 0;
    const int B0_OFF = A_OFF + 128 * PITCH * 2;    // 34816
    const int B1_OFF = B0_OFF + 128 * PITCH * 2;   // 69632
    uint32_t sb = smem_u32(sm);
    int tid = threadIdx.x;
    int w = tid >> 5, lane = tid & 31;
    int n0 = blockIdx.x * 128;

    // y tile (fp16) -> padded A smem
    for (int idx = tid; idx < 128 * 64; idx += 256) {
        int row = idx >> 6, c2 = idx & 63;
        uint32_t v = (n0 + row < NN) ? g_yh[(size_t)(n0 + row) * 64 + c2] : 0u;
        *(uint32_t*)(sm + A_OFF + row * (PITCH * 2) + c2 * 4) = v;
    }
    // async-load W_0 into B0
    {
        const uint4* sh = (const uint4*)g_Wh;
        for (int i = tid; i < 2048; i += 256) {
            int f = i >> 4, seg = i & 15;
            cp_async16(sb + B0_OFF + f * (PITCH * 2) + seg * 16, sh + i);
        }
        asm volatile("cp.async.commit_group;" ::: "memory");
    }

    int a_row = lane & 15, a_cb = (lane >> 4) * 8;
    int b_row = ((lane >> 4) * 8) + (lane & 7);
    int b_kb = ((lane >> 3) & 1) * 8;
    const float4* bmt = (const float4*)g_BM;

    for (int k = 0; k < 7; k++) {
        asm volatile("cp.async.wait_group 0;" ::: "memory");
        __syncthreads();   // W_k resident; prior iter's reads of the other buffer done
        // prefetch W_{k+1} into the other buffer (overlaps this iter's MMA)
        if (k < 6) {
            const uint4* sh = (const uint4*)(g_Wh + (k + 1) * TILE_GB);
            int boff = ((k + 1) & 1) ? B1_OFF : B0_OFF;
            for (int i = tid; i < 2048; i += 256) {
                int f = i >> 4, seg = i & 15;
                cp_async16(sb + boff + f * (PITCH * 2) + seg * 16, sh + i);
            }
            asm volatile("cp.async.commit_group;" ::: "memory");
        }
        uint32_t Bb = sb + ((k & 1) ? B1_OFF : B0_OFF);

        float acc[16][4];
        #pragma unroll
        for (int t = 0; t < 16; t++)
            #pragma unroll
            for (int j = 0; j < 4; j++) acc[t][j] = 0.f;

        #pragma unroll
        for (int ks = 0; ks < 8; ks++) {
            uint32_t a0, a1, a2, a3;
            uint32_t aaddr = sb + A_OFF + (w * 16 + a_row) * (PITCH * 2) + (ks * 16 + a_cb) * 2;
            asm volatile("ldmatrix.sync.aligned.m8n8.x4.shared.b16 {%0,%1,%2,%3}, [%4];"
                         : "=r"(a0), "=r"(a1), "=r"(a2), "=r"(a3) : "r"(aaddr));
            #pragma unroll
            for (int p = 0; p < 8; p++) {
                uint32_t b0, b1, b2, b3;
                uint32_t baddr = Bb + (p * 16 + b_row) * (PITCH * 2) + (ks * 16 + b_kb) * 2;
                asm volatile("ldmatrix.sync.aligned.m8n8.x4.shared.b16 {%0,%1,%2,%3}, [%4];"
                             : "=r"(b0), "=r"(b1), "=r"(b2), "=r"(b3) : "r"(baddr));
                asm volatile(
                    "mma.sync.aligned.m16n8k16.row.col.f32.f16.f16.f32 "
                    "{%0,%1,%2,%3}, {%4,%5,%6,%7}, {%8,%9}, {%0,%1,%2,%3};"
                    : "+f"(acc[2*p][0]), "+f"(acc[2*p][1]), "+f"(acc[2*p][2]), "+f"(acc[2*p][3])
                    : "r"(a0), "r"(a1), "r"(a2), "r"(a3), "r"(b0), "r"(b1));
                asm volatile(
                    "mma.sync.aligned.m16n8k16.row.col.f32.f16.f16.f32 "
                    "{%0,%1,%2,%3}, {%4,%5,%6,%7}, {%8,%9}, {%0,%1,%2,%3};"
                    : "+f"(acc[2*p+1][0]), "+f"(acc[2*p+1][1]), "+f"(acc[2*p+1][2]), "+f"(acc[2*p+1][3])
                    : "r"(a0), "r"(a1), "r"(a2), "r"(a3), "r"(b2), "r"(b3));
            }
        }

        int gr = lane >> 2, cq = (lane & 3) * 2;
        float zA0 = 0.f, zA1 = 0.f, zA2 = 0.f, zB0 = 0.f, zB1 = 0.f, zB2 = 0.f;
        #pragma unroll
        for (int nt = 0; nt < 16; nt++) {
            float4 m0 = __ldg(&bmt[k * HH + nt * 8 + cq]);
            float4 m1 = __ldg(&bmt[k * HH + nt * 8 + cq + 1]);
            float hA0 = fmaxf(acc[nt][0] + m0.x, 0.f);
            float hA1 = fmaxf(acc[nt][1] + m1.x, 0.f);
            float hB0 = fmaxf(acc[nt][2] + m0.x, 0.f);
            float hB1 = fmaxf(acc[nt][3] + m1.x, 0.f);
            zA0 = fmaf(hA0, m0.y, fmaf(hA1, m1.y, zA0));
            zA1 = fmaf(hA0, m0.z, fmaf(hA1, m1.z, zA1));
            zA2 = fmaf(hA0, m0.w, fmaf(hA1, m1.w, zA2));
            zB0 = fmaf(hB0, m0.y, fmaf(hB1, m1.y, zB0));
            zB1 = fmaf(hB0, m0.z, fmaf(hB1, m1.z, zB1));
            zB2 = fmaf(hB0, m0.w, fmaf(hB1, m1.w, zB2));
        }
        #pragma unroll
        for (int off = 1; off < 4; off <<= 1) {
            zA0 += __shfl_xor_sync(0xffffffffu, zA0, off);
            zA1 += __shfl_xor_sync(0xffffffffu, zA1, off);
            zA2 += __shfl_xor_sync(0xffffffffu, zA2, off);
            zB0 += __shfl_xor_sync(0xffffffffu, zB0, off);
            zB1 += __shfl_xor_sync(0xffffffffu, zB1, off);
            zB2 += __shfl_xor_sync(0xffffffffu, zB2, off);
        }
        if ((lane & 3) == 0) {
            int colbase = (k < 5) ? 3 * k : 15 + 2 * (k - 5);
            int ncol = (k < 5) ? 3 : 2;
            int rowA = n0 + w * 16 + gr, rowB = rowA + 8;
            if (rowA < NN) {
                float di = g_dinv[rowA];
                __half* zp = &g_Zh[(size_t)rowA * ZC + colbase];
                zp[0] = __float2half_rn(zA0 * di);
                zp[1] = __float2half_rn(zA1 * di);
                if (ncol == 3) zp[2] = __float2half_rn(zA2 * di);
            }
            if (rowB < NN) {
                float di = g_dinv[rowB];
                __half* zp = &g_Zh[(size_t)rowB * ZC + colbase];
                zp[0] = __float2half_rn(zB0 * di);
                zp[1] = __float2half_rn(zB1 * di);
                if (ncol == 3) zp[2] = __float2half_rn(zB2 * di);
            }
        }
    }
}

// ================= fused CSR-aggregate + softmax (warp per node) =================
__global__ void k_softmax_fused(float* __restrict__ out) {
    int n = (blockIdx.x * blockDim.x + threadIdx.x) >> 5;
    int lane = threadIdx.x & 31;
    if (n >= NN) return;
    bool active = lane < 19;
    int zlane = active ? lane : 0;
    float acc = active ? __half2float(g_Zh[(size_t)n * ZC + lane]) : 0.f;
    int end = g_row[n], e = end - g_cnt[n];
    for (; e + 3 < end; e += 4) {
        int s0 = g_srcl[e], s1 = g_srcl[e + 1], s2 = g_srcl[e + 2], s3 = g_srcl[e + 3];
        float v0 = __half2float(g_Zh[(size_t)s0 * ZC + zlane]);
        float v1 = __half2float(g_Zh[(size_t)s1 * ZC + zlane]);
        float v2 = __half2float(g_Zh[(size_t)s2 * ZC + zlane]);
        float v3 = __half2float(g_Zh[(size_t)s3 * ZC + zlane]);
        acc += (v0 + v1) + (v2 + v3);
    }
    for (; e < end; e++) {
        int s0 = g_srcl[e];
        acc += __half2float(g_Zh[(size_t)s0 * ZC + zlane]);
    }
    float di = g_dinv[n];
    float p = active ? fmaf(acc, di, g_c[lane]) : -1e30f;

    int base, ncol, j;
    if (lane < 15) { base = lane - (lane % 3); ncol = 3; j = lane - base; }
    else { base = 15 + ((lane - 15) & ~1); ncol = 2; j = lane - base; }
    float v0 = __shfl_sync(0xffffffffu, p, base);
    float v1 = __shfl_sync(0xffffffffu, p, base + 1);
    float v2 = (ncol == 3) ? __shfl_sync(0xffffffffu, p, base + 2) : -1e30f;
    float m = fmaxf(v0, fmaxf(v1, v2));
    float sum = __expf(v0 - m) + __expf(v1 - m) + ((ncol == 3) ? __expf(v2 - m) : 0.f);
    float mine = __expf(p - m) / sum;
    if (active)
        out[(long)base * NN + (long)n * ncol + j] = mine;
}

extern "C" void kernel_launch(void* const* d_in, const int* in_sizes, int n_in,
                              void* d_out, int out_size) {
    const float* x   = (const float*)d_in[0];
    const int*   ei  = (const int*)d_in[1];
    const float* gw_ = (const float*)d_in[2];
    const float* gb  = (const float*)d_in[3];
    const float* r3w = (const float*)d_in[4];
    const float* r3b = (const float*)d_in[5];
    const float* r2w = (const float*)d_in[6];
    const float* r2b = (const float*)d_in[7];
    float* out = (float*)d_out;

    const int SMEM = 3 * 128 * PITCH * 2;   // 104448: A + 2x W buffers
    static int once = 0;
    if (!once) {
        cudaFuncSetAttribute(k_branch, cudaFuncAttributeMaxDynamicSharedMemorySize, SMEM);
        once = 1;
    }

    // CSR build
    k_init<<<(NN + 255) / 256, 256>>>();
    k_count<<<(NE / 4 + 255) / 256, 256>>>((const int4*)(ei + NE));
    k_scan1<<<NSCAN, SCAN_BLK>>>();
    k_scan3<<<(NN + 255) / 256, 256>>>();
    k_scatter<<<(NE + 255) / 256, 256>>>(ei);
    // fp16 conversions + weight prep
    k_xh<<<(NN * 32 + 255) / 256, 256>>>((const float4*)x);
    k_mc<<<(19 * HH + 127) / 128, 128>>>(gw_, gb, r3w, r3b, r2w, r2b);
    k_prep_w<<<(7 * 128 * 64 + 127) / 128, 128>>>(gw_);
    // main pipeline
    k_agg_y_csr<<<(NN * 32 + 255) / 256, 256>>>();
    k_branch<<<NB, 256, SMEM>>>();
    k_softmax_fused<<<(NN * 32 + 255) / 256, 256>>>(out);
}